// round 6
// baseline (speedup 1.0000x reference)
#include <cuda_runtime.h>

// x: (B=16, C=512, H=62, W=62) fp32, row-major.
// 9 regions: 2x2 patches at (y,x), y,x in {0,30,60}. flat base = y*62 + x.
// Patch elements: base, base+1, base+62, base+63. Pairs: (2k, 2k+1).
#define HW      3844
#define WIDTH   62
#define CHN     512
#define NPAIR   8
#define NREG    9
#define NCHUNK  16
#define NBLK    (NCHUNK * NPAIR)   // 128
#define EPSV    1e-6f

__constant__ int c_posbase[9] = {0, 30, 60, 1860, 1890, 1920, 3720, 3750, 3780};
// region -> 5 negative region indices (region 8 = {2,4,5,6,7}; verified vs ref)
__constant__ int c_negidx[9][5] = {
    {1,3,4,2,6},
    {0,2,3,4,5},
    {0,1,4,5,8},
    {0,1,4,6,7},
    {0,1,3,5,7},
    {1,2,4,7,8},
    {0,3,4,7,8},
    {3,4,5,6,8},
    {2,4,5,6,7}
};

// Partials: [pair][chunk][region][{S,D1,D2}] — fully overwritten every launch.
__device__ float        g_partial[NPAIR][NCHUNK][NREG][3];
__device__ unsigned int g_count;   // zero-init; last block resets each launch

struct P { float a, b, c, d, rn, ss; };   // rn = rsqrt(ss), hoisted per patch

// exp(cos(p,q)/TEMP): cos = dot / max(na*nb, EPS), TEMP = 0.1
__device__ __forceinline__ float cexp(const P& p, const P& q) {
    float dot = fmaf(p.a, q.a, fmaf(p.b, q.b, fmaf(p.c, q.c, p.d * q.d)));
    float d2  = p.ss * q.ss;                        // (na*nb)^2
    float cosv = (d2 >= EPSV * EPSV) ? dot * (p.rn * q.rn) : dot * (1.0f / EPSV);
    return __expf(cosv * 10.0f);
}

__global__ __launch_bounds__(NREG * 32)
void lcl_fused(const float* __restrict__ x, float* __restrict__ out) {
    const int pair  = blockIdx.y;                   // 0..7
    const int chunk = blockIdx.x;                   // 0..15
    const int tid   = threadIdx.x;
    const int r     = tid >> 5;                     // region = warp id, 0..8
    const int lane  = tid & 31;
    const int c     = chunk * 32 + lane;            // channel 0..511

    // SoA patch stage: [field][plane][region][lane]; lane-stride-1 -> no conflicts
    __shared__ float sP[6][2][NREG][32];
    __shared__ float shv[NPAIR * NREG];
    __shared__ int   s_isLast;

    P a1, a2;
    {
        const float* p1 = x + ((size_t)(2 * pair) * CHN + (size_t)c) * HW; // batch 2k
        const float* p2 = p1 + (size_t)CHN * HW;                           // batch 2k+1
        const int pb = c_posbase[r];

        float2 u01 = *reinterpret_cast<const float2*>(p1 + pb);
        float2 u23 = *reinterpret_cast<const float2*>(p1 + pb + WIDTH);
        float2 v01 = *reinterpret_cast<const float2*>(p2 + pb);
        float2 v23 = *reinterpret_cast<const float2*>(p2 + pb + WIDTH);

        a1.a = u01.x; a1.b = u01.y; a1.c = u23.x; a1.d = u23.y;
        a1.ss = fmaf(a1.a, a1.a, fmaf(a1.b, a1.b, fmaf(a1.c, a1.c, a1.d * a1.d)));
        a1.rn = rsqrtf(a1.ss);
        a2.a = v01.x; a2.b = v01.y; a2.c = v23.x; a2.d = v23.y;
        a2.ss = fmaf(a2.a, a2.a, fmaf(a2.b, a2.b, fmaf(a2.c, a2.c, a2.d * a2.d)));
        a2.rn = rsqrtf(a2.ss);

        sP[0][0][r][lane] = a1.a;  sP[0][1][r][lane] = a2.a;
        sP[1][0][r][lane] = a1.b;  sP[1][1][r][lane] = a2.b;
        sP[2][0][r][lane] = a1.c;  sP[2][1][r][lane] = a2.c;
        sP[3][0][r][lane] = a1.d;  sP[3][1][r][lane] = a2.d;
        sP[4][0][r][lane] = a1.rn; sP[4][1][r][lane] = a2.rn;
        sP[5][0][r][lane] = a1.ss; sP[5][1][r][lane] = a2.ss;
    }
    __syncthreads();

    float S  = cexp(a1, a2);
    float D1 = 0.0f, D2 = 0.0f;

#pragma unroll
    for (int n = 0; n < 5; n++) {
        const int j = c_negidx[r][n];
        P b1, b2;
        b1.a  = sP[0][0][j][lane];  b2.a  = sP[0][1][j][lane];
        b1.b  = sP[1][0][j][lane];  b2.b  = sP[1][1][j][lane];
        b1.c  = sP[2][0][j][lane];  b2.c  = sP[2][1][j][lane];
        b1.d  = sP[3][0][j][lane];  b2.d  = sP[3][1][j][lane];
        b1.rn = sP[4][0][j][lane];  b2.rn = sP[4][1][j][lane];
        b1.ss = sP[5][0][j][lane];  b2.ss = sP[5][1][j][lane];
        D1 += cexp(a1, b1) + cexp(a1, b2);
        D2 += cexp(a2, b2) + cexp(a2, b1);
    }

#pragma unroll
    for (int o = 16; o; o >>= 1) {
        S  += __shfl_xor_sync(0xffffffffu, S,  o);
        D1 += __shfl_xor_sync(0xffffffffu, D1, o);
        D2 += __shfl_xor_sync(0xffffffffu, D2, o);
    }
    if (lane == 0) {
        g_partial[pair][chunk][r][0] = S;
        g_partial[pair][chunk][r][1] = D1;
        g_partial[pair][chunk][r][2] = D2;
        __threadfence();                            // partials visible before ticket
    }
    __syncthreads();

    if (tid == 0)
        s_isLast = (atomicAdd(&g_count, 1u) == NBLK - 1u);
    __syncthreads();

    if (s_isLast) {
        if (tid < NPAIR * NREG) {                   // 72 cells, 3 warps active
            const int p  = tid / NREG;
            const int rr = tid % NREG;
            float Sx = 0.0f, d1 = 0.0f, d2 = 0.0f;
#pragma unroll
            for (int ch = 0; ch < NCHUNK; ch++) {
                Sx += __ldcg(&g_partial[p][ch][rr][0]);
                d1 += __ldcg(&g_partial[p][ch][rr][1]);
                d2 += __ldcg(&g_partial[p][ch][rr][2]);
            }
            shv[tid] = logf((Sx + d1) / Sx) + logf((Sx + d2) / Sx);
        }
        __syncthreads();
        if (tid == 0) {
            float tot = 0.0f;
#pragma unroll
            for (int i = 0; i < NPAIR * NREG; i++) tot += shv[i];
            out[0] = tot * (1.0f / 144.0f);         // / BATCH(16) / N_REGIONS(9)
            g_count = 0;                            // reset for next graph replay
        }
    }
}

extern "C" void kernel_launch(void* const* d_in, const int* in_sizes, int n_in,
                              void* d_out, int out_size) {
    const float* x = (const float*)d_in[0];
    float* out = (float*)d_out;
    (void)in_sizes; (void)n_in; (void)out_size;

    dim3 grid(NCHUNK, NPAIR, 1);                    // 128 blocks, one wave
    dim3 block(NREG * 32, 1, 1);                    // 288 threads = 9 warps
    lcl_fused<<<grid, block>>>(x, out);
}